// round 16
// baseline (speedup 1.0000x reference)
#include <cuda_runtime.h>
#include <cstdint>

#define KDIM     256
#define NCOLS    40          // 10 classes * 4 centroids
#define NCLASSES 10
#define KCENT    4
#define BM       128         // rows per CTA tile: 8 warps x 16 rows (one m16)
#define NTHREADS 256
#define NBUF     2           // half-K double buffer per warp
#define STAGE_F4 512         // 16 rows * 32 float4 (8 KB)

__device__ __forceinline__ void cp16(uint32_t dst, const float* src) {
    asm volatile("cp.async.cg.shared.global [%0], [%1], 16;"
                 :: "r"(dst), "l"(src) : "memory");
}
__device__ __forceinline__ void cp_commit() {
    asm volatile("cp.async.commit_group;" ::: "memory");
}
__device__ __forceinline__ void cp_wait1() {
    asm volatile("cp.async.wait_group 1;" ::: "memory");
}
__device__ __forceinline__ float tf32r(float x) {
    uint32_t u;
    asm("cvt.rna.tf32.f32 %0, %1;" : "=r"(u) : "f"(x));
    return __uint_as_float(u);
}

// ---------------------------------------------------------------------------
// Hot kernel: persistent CTAs (1/SM), 8 warps, 256 threads (proven geometry).
// DRAM-page-friendly A streaming: each cp.async = one row's contiguous 512B;
// per 2KB page: 2 visits x 1KB (vs 8 x 256B before). Warp = one m16 tile.
// Double-buffered half-K stages (8KB each), wait_group 1.
// Bank swizzle: odd rows store float4 j at j^4 (XOR 64B) -> conflict-free
// STS and fragment LDS.128. B fragments computed in-CTA (R15 short chain).
// smem: A 8 warps * 2 * 8KB = 128KB + B 40KB = 168KB.
// Bsm float4 index = ((c*5 + nt)*2 + ii)*32 + (g*4+q), component f, holding
// B_nat[n = nt*8 + g][nat_k = c*32 + 16*ii + 4*q + f].
// ---------------------------------------------------------------------------
extern __shared__ float4 smem4[];

__global__ void __launch_bounds__(NTHREADS, 1)
gemm_kernel(const float* __restrict__ codes,
            const float* __restrict__ cents,
            float* __restrict__ out, int ntiles) {
    float4* const Asm = smem4;            // 8192 float4 (128 KB)
    float4* const Bsm = smem4 + 8192;     // 2560 float4 (40 KB)

    const int tid  = threadIdx.x;
    const int lane = tid & 31;
    const int warp = tid >> 5;
    const int g = lane >> 2;     // 0..7
    const int q = lane & 3;      // 0..3
    const int b = blockIdx.x;
    const int G = gridDim.x;

    const int myn = (ntiles > b) ? ((ntiles - b - 1) / G + 1) : 0;
    if (myn == 0) return;
    const int total = myn * 2;             // half-K chunks

    // byte address of this thread's region (stage 0)
    const uint32_t abase =
        (uint32_t)__cvta_generic_to_shared(Asm) +
        (uint32_t)warp * (NBUF * STAGE_F4 * 16);
    const uint32_t le = (uint32_t)lane * 16u;          // even-row lane slot
    const uint32_t lo = (uint32_t)(lane ^ 4) * 16u;    // odd-row (swizzled)

    // 32-bit element-offset addressing
    const uint32_t boff0   = ((uint32_t)b * BM + (uint32_t)(warp * 16)) * KDIM
                           + (uint32_t)(4 * lane);
    const uint32_t gstride = (uint32_t)G * BM * KDIM;

    // Issue one half-K chunk fc: 16 rows x 512B contiguous, 1 commit group.
    auto issue = [&](int fc) {
        fc = fc < total - 1 ? fc : total - 1;     // clamp: rewrites same bytes
        const uint32_t dst = abase + (uint32_t)(fc & 1) * (STAGE_F4 * 16);
        const float* ap = codes + (boff0 + (uint32_t)(fc >> 1) * gstride
                                   + (uint32_t)((fc & 1) * 128));
        #pragma unroll
        for (int r = 0; r < 16; r++)
            cp16(dst + (uint32_t)(r * 512) + ((r & 1) ? lo : le),
                 ap + r * KDIM);
        cp_commit();
    };

    // Prologue: both buffers in flight.
    issue(0); issue(1);

    // In-CTA B prep (overlapped with A prologue), identical to R15.
    {
        const int sl  = (lane >> 3) * 5;
        const int ii  = (lane >> 2) & 1;
        const int col = (lane & 3);
        #pragma unroll
        for (int vv = 0; vv < 5; vv++) {
            const int v = warp * 5 + vv;
            const float4* src4 = reinterpret_cast<const float4*>(cents + v * KDIM);
            const float4 v0 = src4[lane];
            const float4 v1 = src4[lane + 32];
            float s = v0.x * v0.x + v0.y * v0.y + v0.z * v0.z + v0.w * v0.w
                    + v1.x * v1.x + v1.y * v1.y + v1.z * v1.z + v1.w * v1.w;
            #pragma unroll
            for (int off = 16; off; off >>= 1)
                s += __shfl_xor_sync(0xffffffffu, s, off);
            const float inv = 1.f / fmaxf(sqrtf(s), 1e-12f);
            const int nt = v >> 3;
            const int gg = v & 7;
            float4 o0, o1;
            o0.x = tf32r(v0.x * inv); o0.y = tf32r(v0.y * inv);
            o0.z = tf32r(v0.z * inv); o0.w = tf32r(v0.w * inv);
            o1.x = tf32r(v1.x * inv); o1.y = tf32r(v1.y * inv);
            o1.z = tf32r(v1.z * inv); o1.w = tf32r(v1.w * inv);
            Bsm[((sl + nt) * 2 + ii) * 32 + gg * 4 + col] = o0;       // c
            Bsm[((sl + 20 + nt) * 2 + ii) * 32 + gg * 4 + col] = o1;  // c+4
        }
    }
    __syncthreads();

    const float4* const aw = Asm + warp * (NBUF * STAGE_F4);
    const int sw = (g & 1) << 2;          // row-parity swizzle for fragments

    for (int ti = 0; ti < myn; ti++) {
        float acc[5][4];
        #pragma unroll
        for (int n = 0; n < 5; n++)
            #pragma unroll
            for (int j = 0; j < 4; j++) acc[n][j] = 0.f;

        #pragma unroll
        for (int hf = 0; hf < 2; hf++) {
            const int fc = ti * 2 + hf;
            cp_wait1();                   // chunk fc complete
            const float4* const ab = aw + (fc & 1) * STAGE_F4;

            // Read ALL A fragments for this half-K (16 LDS.128), then refill.
            float4 A0[4][2], A8[4][2];    // [subchunk][i] rows g / g+8
            #pragma unroll
            for (int s = 0; s < 4; s++) {
                const int i0 = (8 * s + q) ^ sw;
                const int i1 = (8 * s + q + 4) ^ sw;
                A0[s][0] = ab[g * 32 + i0];
                A0[s][1] = ab[g * 32 + i1];
                A8[s][0] = ab[(g + 8) * 32 + i0];
                A8[s][1] = ab[(g + 8) * 32 + i1];
            }

            issue(fc + 2);                // refill this buffer (overlap MMAs)

            #pragma unroll
            for (int s = 0; s < 4; s++) {
                const int c = hf * 4 + s; // global k-32 chunk for B
                #pragma unroll
                for (int nt = 0; nt < 5; nt++) {
                    const float4 wb0 = Bsm[((c * 5 + nt) * 2 + 0) * 32 + lane];
                    const float4 wb1 = Bsm[((c * 5 + nt) * 2 + 1) * 32 + lane];
                    #pragma unroll
                    for (int m = 0; m < 4; m++) {
                        const float4 wb = (m < 2) ? wb0 : wb1;
                        const float4 pa = A0[s][m >> 1];
                        const float4 pb = A8[s][m >> 1];
                        const uint32_t b0 = __float_as_uint((m & 1) ? wb.z : wb.x);
                        const uint32_t b1 = __float_as_uint((m & 1) ? wb.w : wb.y);
                        const uint32_t a0 = __float_as_uint((m & 1) ? pa.z : pa.x);
                        const uint32_t a1 = __float_as_uint((m & 1) ? pb.z : pb.x);
                        const uint32_t a2 = __float_as_uint((m & 1) ? pa.w : pa.y);
                        const uint32_t a3 = __float_as_uint((m & 1) ? pb.w : pb.y);
                        asm volatile(
                            "mma.sync.aligned.m16n8k8.row.col.f32.tf32.tf32.f32 "
                            "{%0,%1,%2,%3}, {%4,%5,%6,%7}, {%8,%9}, {%0,%1,%2,%3};"
                            : "+f"(acc[nt][0]), "+f"(acc[nt][1]),
                              "+f"(acc[nt][2]), "+f"(acc[nt][3])
                            : "r"(a0), "r"(a1), "r"(a2), "r"(a3),
                              "r"(b0), "r"(b1));
                    }
                }
            }
        }

        // Epilogue: acc[nt][0,1] -> row row0 ; acc[nt][2,3] -> row0+8.
        const long row0 = (long)(b + ti * G) * BM + warp * 16 + g;
        float* const obase = out + row0 * NCLASSES;
        #pragma unroll
        for (int nt = 0; nt < 5; nt++) {
            float m0 = fmaxf(acc[nt][0], acc[nt][1]);
            float m1 = fmaxf(acc[nt][2], acc[nt][3]);
            m0 = fmaxf(m0, __shfl_xor_sync(0xffffffffu, m0, 1));
            m1 = fmaxf(m1, __shfl_xor_sync(0xffffffffu, m1, 1));
            const int cls = nt * 2 + (q >> 1);
            if ((q & 1) == 0) {
                __stcs(obase + cls, 1.f - m0);
                __stcs(obase + 8 * NCLASSES + cls, 1.f - m1);
            }
        }
    }
}

// ---------------------------------------------------------------------------
// Tail: remaining (< BM) rows, plain fp32, self-contained.
// Never launched when nrows % 128 == 0.
// ---------------------------------------------------------------------------
__global__ void tail_kernel(const float* __restrict__ codes,
                            const float* __restrict__ cents,
                            float* __restrict__ out,
                            long rbase, int nrows) {
    const long row = rbase + blockIdx.x * blockDim.x + threadIdx.x;
    if (row >= nrows) return;
    const float* a = codes + row * KDIM;
    float best[NCLASSES];
    #pragma unroll
    for (int c = 0; c < NCLASSES; c++) best[c] = -1e30f;
    for (int v = 0; v < NCOLS; v++) {
        const float* bp = cents + v * KDIM;
        float nrm = 0.f, s = 0.f;
        for (int k = 0; k < KDIM; k++) {
            nrm += bp[k] * bp[k];
            s   += a[k] * bp[k];
        }
        s *= 1.f / fmaxf(sqrtf(nrm), 1e-12f);
        const int c = v / KCENT;
        best[c] = fmaxf(best[c], s);
    }
    #pragma unroll
    for (int c = 0; c < NCLASSES; c++)
        out[row * NCLASSES + c] = 1.f - best[c];
}

// ---------------------------------------------------------------------------
extern "C" void kernel_launch(void* const* d_in, const int* in_sizes, int n_in,
                              void* d_out, int out_size) {
    const float* codes = (const float*)d_in[0];   // (B, 256) f32
    const float* cents = (const float*)d_in[1];   // (10, 4, 256) f32
    float* out = (float*)d_out;                   // (B, 10) f32

    const int nrows  = in_sizes[0] / KDIM;
    const int ntiles = nrows / BM;
    const int tail   = nrows - ntiles * BM;

    const int smem_bytes = (8192 + 2560) * (int)sizeof(float4);  // 172032

    cudaFuncSetAttribute(gemm_kernel,
                         cudaFuncAttributeMaxDynamicSharedMemorySize,
                         smem_bytes);

    int nsm = 0;
    cudaDeviceGetAttribute(&nsm, cudaDevAttrMultiProcessorCount, 0);
    if (nsm <= 0) nsm = 148;

    if (ntiles > 0) {
        const int grid = ntiles < nsm ? ntiles : nsm;
        gemm_kernel<<<grid, NTHREADS, smem_bytes>>>(codes, cents, out, ntiles);
    }
    if (tail > 0) {
        const int tb = (tail + 255) / 256;
        tail_kernel<<<tb, 256>>>(codes, cents, out, (long)ntiles * BM, nrows);
    }
}